// round 1
// baseline (speedup 1.0000x reference)
#include <cuda_runtime.h>

#define BB   1024
#define TT   256
#define CC   384
#define HS   64

typedef unsigned long long ull;

// Scratch for Q, K, V projections (device globals: allocation-free).
__device__ float Qg[BB * TT * HS];
__device__ float Kg[BB * TT * HS];
__device__ float Vg[BB * TT * HS];

// ---------------- packed f32x2 helpers (Blackwell FFMA2 path) ----------------
__device__ __forceinline__ ull pack2(float lo, float hi) {
    ull d; asm("mov.b64 %0, {%1, %2};" : "=l"(d) : "f"(lo), "f"(hi)); return d;
}
__device__ __forceinline__ void unpack2(ull v, float& lo, float& hi) {
    asm("mov.b64 {%0, %1}, %2;" : "=f"(lo), "=f"(hi) : "l"(v));
}
__device__ __forceinline__ ull fma2(ull a, ull b, ull c) {
    ull d; asm("fma.rn.f32x2 %0, %1, %2, %3;" : "=l"(d) : "l"(a), "l"(b), "l"(c)); return d;
}
__device__ __forceinline__ ull mul2(ull a, ull b) {
    ull d; asm("mul.rn.f32x2 %0, %1, %2;" : "=l"(d) : "l"(a), "l"(b)); return d;
}
__device__ __forceinline__ ull add2(ull a, ull b) {
    ull d; asm("add.rn.f32x2 %0, %1, %2;" : "=l"(d) : "l"(a), "l"(b)); return d;
}

// ============================================================================
// Kernel 1: QKV projection.
// X [N=262144, 384] @ {Wq,Wk,Wv} [384, 64] -> Qg/Kg/Vg [N, 64].
// Tile: BM=64 rows, BN=192 cols (Q|K|V concatenated), BK=32.
// 256 threads as 16(tx) x 16(ty); thread tile TM=4 rows x TN=12 cols,
// accumulated as 6 f32x2 pairs per row.
// ============================================================================
#define BK 32
#define XS_STRIDE 40   // BK + 8 pad: keeps float4 alignment, kills bank conflicts

__global__ __launch_bounds__(256, 2)
void qkv_kernel(const float* __restrict__ X,
                const float* __restrict__ Wq,
                const float* __restrict__ Wk,
                const float* __restrict__ Wv)
{
    __shared__ float Xs[64][XS_STRIDE];   // [row][k]
    __shared__ float Ws[BK][192];         // [k][col], col = m*64 + hs

    const int tid = threadIdx.x;
    const int tx  = tid & 15;             // col group: 12 output cols
    const int ty  = tid >> 4;             // row group: 4 rows
    const int row0 = blockIdx.x * 64;

    ull acc[4][6];
#pragma unroll
    for (int i = 0; i < 4; i++)
#pragma unroll
        for (int j = 0; j < 6; j++) acc[i][j] = pack2(0.f, 0.f);

    for (int k0 = 0; k0 < CC; k0 += BK) {
        // --- stage X tile: 64 rows x 32 cols ---
        {
            const int r  = tid >> 3;       // 0..31
            const int c4 = (tid & 7) << 2; // 0,4,..,28
#pragma unroll
            for (int it = 0; it < 2; it++) {
                float4 v = *(const float4*)&X[(size_t)(row0 + r + 32 * it) * CC + k0 + c4];
                *(float4*)&Xs[r + 32 * it][c4] = v;
            }
        }
        // --- stage W tile: 32 rows x 192 cols (3 matrices) ---
        {
#pragma unroll
            for (int it = 0; it < 6; it++) {
                const int i  = tid + 256 * it;        // 0..1535
                const int m  = i >> 9;                // matrix 0..2
                const int rr = (i & 511) >> 4;        // k row 0..31
                const int cc = (i & 15) << 2;         // 0..60
                const float* W = (m == 0) ? Wq : ((m == 1) ? Wk : Wv);
                float4 v = *(const float4*)&W[(size_t)(k0 + rr) * HS + cc];
                *(float4*)&Ws[rr][m * 64 + cc] = v;
            }
        }
        __syncthreads();

#pragma unroll
        for (int kk = 0; kk < BK; kk++) {
            ull a2[4];
#pragma unroll
            for (int i = 0; i < 4; i++) {
                float a = Xs[ty * 4 + i][kk];
                a2[i] = pack2(a, a);
            }
            ull b2[6];
#pragma unroll
            for (int v = 0; v < 3; v++) {
                float4 bv = *(const float4*)&Ws[kk][tx * 12 + 4 * v];
                b2[2 * v]     = pack2(bv.x, bv.y);
                b2[2 * v + 1] = pack2(bv.z, bv.w);
            }
#pragma unroll
            for (int i = 0; i < 4; i++)
#pragma unroll
                for (int j = 0; j < 6; j++)
                    acc[i][j] = fma2(a2[i], b2[j], acc[i][j]);
        }
        __syncthreads();
    }

    // --- store: col = tx*12 + 2j (even, never straddles a 64-col boundary) ---
#pragma unroll
    for (int i = 0; i < 4; i++) {
        const size_t row = row0 + ty * 4 + i;
#pragma unroll
        for (int j = 0; j < 6; j++) {
            const int col = tx * 12 + 2 * j;
            const int m   = col >> 6;
            const int hs  = col & 63;
            float lo, hi; unpack2(acc[i][j], lo, hi);
            float* dst = (m == 0) ? Qg : ((m == 1) ? Kg : Vg);
            dst[row * HS + hs]     = lo;
            dst[row * HS + hs + 1] = hi;
        }
    }
}

// ============================================================================
// Kernel 2: fused causal attention, one thread per query row.
// grid = (2 query-halves, B). CTA stages K,V rows [0, kn) in smem
// (kn = 128 for half 0, 256 for half 1). Online softmax, f32x2 math.
// ============================================================================
__global__ __launch_bounds__(128, 1)
void attn_kernel(float* __restrict__ out)
{
    extern __shared__ float sm[];
    const int half = blockIdx.x;
    const int b    = blockIdx.y;
    const int tid  = threadIdx.x;
    const int kn   = 128 * (half + 1);

    float* Ks = sm;
    float* Vs = sm + kn * HS;

    const float* Kb = Kg + (size_t)b * TT * HS;
    const float* Vb = Vg + (size_t)b * TT * HS;

    // stage K,V (coalesced float4)
    const int nv4 = kn * (HS / 4);
    for (int i = tid; i < nv4; i += 128) {
        ((float4*)Ks)[i] = ((const float4*)Kb)[i];
        ((float4*)Vs)[i] = ((const float4*)Vb)[i];
    }

    // load this thread's query row into f32x2 registers
    const int qrow = half * 128 + tid;
    const float* qptr = Qg + ((size_t)b * TT + qrow) * HS;
    ull q2[32];
#pragma unroll
    for (int i = 0; i < 16; i++) {
        float4 v = *(const float4*)(qptr + 4 * i);
        q2[2 * i]     = pack2(v.x, v.y);
        q2[2 * i + 1] = pack2(v.z, v.w);
    }

    __syncthreads();

    float m = -1e30f, l = 0.f;
    ull acc2[32];
#pragma unroll
    for (int d = 0; d < 32; d++) acc2[d] = pack2(0.f, 0.f);

    const int kend = qrow + 1;   // causal trip count (<= kn)

    for (int k = 0; k < kend; k++) {
        const ulonglong2* krow = (const ulonglong2*)(Ks + k * HS);
        ull s2[4];
#pragma unroll
        for (int j = 0; j < 4; j++) s2[j] = pack2(0.f, 0.f);
#pragma unroll
        for (int d = 0; d < 16; d++) {
            ulonglong2 kv = krow[d];
            s2[(2 * d)     & 3] = fma2(q2[2 * d],     kv.x, s2[(2 * d)     & 3]);
            s2[(2 * d + 1) & 3] = fma2(q2[2 * d + 1], kv.y, s2[(2 * d + 1) & 3]);
        }
        ull t = add2(add2(s2[0], s2[1]), add2(s2[2], s2[3]));
        float slo, shi; unpack2(t, slo, shi);
        float s = (slo + shi) * 0.125f;   // * HS^-0.5

        const float mn = fmaxf(m, s);
        const float p  = __expf(s - mn);
        if (mn > m) {                      // running max moved: rescale
            const float corr = __expf(m - mn);
            l *= corr;
            const ull c2 = pack2(corr, corr);
#pragma unroll
            for (int d = 0; d < 32; d++) acc2[d] = mul2(acc2[d], c2);
        }
        m = mn;
        l += p;

        const ull p2 = pack2(p, p);
        const ulonglong2* vrow = (const ulonglong2*)(Vs + k * HS);
#pragma unroll
        for (int d = 0; d < 16; d++) {
            ulonglong2 vv = vrow[d];
            acc2[2 * d]     = fma2(p2, vv.x, acc2[2 * d]);
            acc2[2 * d + 1] = fma2(p2, vv.y, acc2[2 * d + 1]);
        }
    }

    const float inv = 1.f / l;
    float* optr = out + ((size_t)b * TT + qrow) * HS;
#pragma unroll
    for (int i = 0; i < 16; i++) {
        float l0, h0, l1, h1;
        unpack2(acc2[2 * i],     l0, h0);
        unpack2(acc2[2 * i + 1], l1, h1);
        float4 v = make_float4(l0 * inv, h0 * inv, l1 * inv, h1 * inv);
        *(float4*)(optr + 4 * i) = v;
    }
}

// ============================================================================
extern "C" void kernel_launch(void* const* d_in, const int* in_sizes, int n_in,
                              void* d_out, int out_size)
{
    const float* x  = (const float*)d_in[0];
    const float* Wq = (const float*)d_in[1];
    const float* Wk = (const float*)d_in[2];
    const float* Wv = (const float*)d_in[3];
    float* out = (float*)d_out;

    (void)in_sizes; (void)n_in; (void)out_size;

    // 1) QKV projection: N/64 = 4096 CTAs
    qkv_kernel<<<(BB * TT) / 64, 256>>>(x, Wq, Wk, Wv);

    // 2) fused causal attention (128 KB dynamic smem for K+V at kn=256)
    const int smem_bytes = TT * HS * 2 * (int)sizeof(float);  // 131072
    cudaFuncSetAttribute(attn_kernel, cudaFuncAttributeMaxDynamicSharedMemorySize, smem_bytes);
    dim3 grid(2, BB);
    attn_kernel<<<grid, 128, smem_bytes>>>(out);
}

// round 3
// speedup vs baseline: 1.6736x; 1.6736x over previous
#include <cuda_runtime.h>
#include <cuda_bf16.h>
#include <cstdint>

#define BB   1024
#define TT   256
#define CC   384
#define HS   64

typedef unsigned long long ull;

// Scratch (device globals: allocation-free).
__device__ float Qg[BB * TT * HS];
__device__ float Kg[BB * TT * HS];
__device__ float Vg[BB * TT * HS];

// Pre-split W, bf16 hi/lo, layout [n=192][k=384] (n = m*64 + hs), k-contiguous.
__device__ __align__(16) __nv_bfloat16 WbH[192 * 384];
__device__ __align__(16) __nv_bfloat16 WbL[192 * 384];

// ---------------- packed f32x2 helpers (attention kernel) ----------------
__device__ __forceinline__ ull pack2(float lo, float hi) {
    ull d; asm("mov.b64 %0, {%1, %2};" : "=l"(d) : "f"(lo), "f"(hi)); return d;
}
__device__ __forceinline__ void unpack2(ull v, float& lo, float& hi) {
    asm("mov.b64 {%0, %1}, %2;" : "=f"(lo), "=f"(hi) : "l"(v));
}
__device__ __forceinline__ ull fma2(ull a, ull b, ull c) {
    ull d; asm("fma.rn.f32x2 %0, %1, %2, %3;" : "=l"(d) : "l"(a), "l"(b), "l"(c)); return d;
}
__device__ __forceinline__ ull mul2(ull a, ull b) {
    ull d; asm("mul.rn.f32x2 %0, %1, %2;" : "=l"(d) : "l"(a), "l"(b)); return d;
}
__device__ __forceinline__ ull add2(ull a, ull b) {
    ull d; asm("add.rn.f32x2 %0, %1, %2;" : "=l"(d) : "l"(a), "l"(b)); return d;
}

// Fast exp(x) for x <= 0, FMA-pipe only (no MUFU). Rel err ~1e-6.
__device__ __forceinline__ float fexp(float x) {
    float t = x * 1.44269504f;
    t = fmaxf(t, -125.0f);
    float fi = floorf(t);
    float f = t - fi;
    float p = 0.0018775767f;
    p = fmaf(p, f, 0.0089893397f);
    p = fmaf(p, f, 0.055826318f);
    p = fmaf(p, f, 0.24015361f);
    p = fmaf(p, f, 0.69315308f);
    p = fmaf(p, f, 1.0f);
    int e = (int)fi;
    return p * __int_as_float((e + 127) << 23);
}

// ---------------- mma.sync wrapper (baseline sm_80+ PTX, no 'a' features) ----
__device__ __forceinline__ void mma16816(float& c0, float& c1, float& c2, float& c3,
                                         uint32_t a0, uint32_t a1, uint32_t a2, uint32_t a3,
                                         uint32_t b0, uint32_t b1) {
    asm volatile(
        "mma.sync.aligned.m16n8k16.row.col.f32.bf16.bf16.f32 "
        "{%0,%1,%2,%3}, {%4,%5,%6,%7}, {%8,%9}, {%0,%1,%2,%3};"
        : "+f"(c0), "+f"(c1), "+f"(c2), "+f"(c3)
        : "r"(a0), "r"(a1), "r"(a2), "r"(a3), "r"(b0), "r"(b1));
}

// ============================================================================
// Kernel 0: split W into bf16 hi/lo at layout [n][k].
// ============================================================================
__global__ void prep_w(const float* __restrict__ Wq,
                       const float* __restrict__ Wk,
                       const float* __restrict__ Wv)
{
    int idx = blockIdx.x * blockDim.x + threadIdx.x;
    if (idx >= 192 * 384) return;
    int n = idx / 384;
    int k = idx % 384;
    int m = n >> 6, hs = n & 63;
    const float* W = (m == 0) ? Wq : ((m == 1) ? Wk : Wv);
    float v = W[k * HS + hs];
    __nv_bfloat16 h = __float2bfloat16(v);
    __nv_bfloat16 l = __float2bfloat16(v - __bfloat162float(h));
    WbH[n * 384 + k] = h;
    WbL[n * 384 + k] = l;
}

// ============================================================================
// Kernel 1: QKV projection via mma.sync bf16 3-pass split GEMM.
// Grid (2048 m-tiles, 2 n-slices). CTA tile 128(M) x 96(N), K chunks of 32.
// 8 warps in 4x2: warp tile 32x48 -> 2 m-tiles x 6 n-tiles of m16n8k16.
// ============================================================================
#define SA 40   // smem k-stride in halves (32 + 8 pad): conflict-free

__global__ __launch_bounds__(256, 2)
void qkv_mma(const float* __restrict__ X)
{
    __shared__ __align__(16) __nv_bfloat16 Ah[128][SA];
    __shared__ __align__(16) __nv_bfloat16 Al[128][SA];
    __shared__ __align__(16) __nv_bfloat16 Bh[96][SA];
    __shared__ __align__(16) __nv_bfloat16 Bl[96][SA];

    const int tid  = threadIdx.x;
    const int lane = tid & 31;
    const int w    = tid >> 5;
    const int wm   = w >> 1;           // 0..3
    const int wn   = w & 1;            // 0..1
    const int m0   = wm * 32;
    const int n0   = wn * 48;
    const int gid  = lane >> 2;
    const int tg   = lane & 3;

    const size_t row0 = (size_t)blockIdx.x * 128;
    const int    s    = blockIdx.y;     // n-slice: global cols s*96 .. s*96+95

    float acc[2][6][4];
#pragma unroll
    for (int i = 0; i < 2; i++)
#pragma unroll
        for (int j = 0; j < 6; j++)
#pragma unroll
            for (int q = 0; q < 4; q++) acc[i][j][q] = 0.f;

    for (int c = 0; c < 12; c++) {
        const int k0 = c * 32;
        __syncthreads();
        // --- stage A: X[row0..row0+127][k0..k0+31] fp32 -> bf16 hi/lo ---
#pragma unroll
        for (int it = 0; it < 4; it++) {
            int i  = tid + 256 * it;      // 0..1023 float4s
            int r  = i >> 3;               // row 0..127
            int c4 = (i & 7) << 2;         // col 0..28
            float4 v = *reinterpret_cast<const float4*>(&X[(row0 + r) * CC + k0 + c4]);
            __nv_bfloat162 h01 = __floats2bfloat162_rn(v.x, v.y);
            __nv_bfloat162 h23 = __floats2bfloat162_rn(v.z, v.w);
            float r0 = v.x - __bfloat162float(h01.x);
            float r1 = v.y - __bfloat162float(h01.y);
            float r2 = v.z - __bfloat162float(h23.x);
            float r3 = v.w - __bfloat162float(h23.y);
            __nv_bfloat162 l01 = __floats2bfloat162_rn(r0, r1);
            __nv_bfloat162 l23 = __floats2bfloat162_rn(r2, r3);
            *reinterpret_cast<uint2*>(&Ah[r][c4]) =
                make_uint2(*reinterpret_cast<uint32_t*>(&h01), *reinterpret_cast<uint32_t*>(&h23));
            *reinterpret_cast<uint2*>(&Al[r][c4]) =
                make_uint2(*reinterpret_cast<uint32_t*>(&l01), *reinterpret_cast<uint32_t*>(&l23));
        }
        // --- stage B: pre-split W rows [s*96 .. +95][k0..k0+31] (pure copies) ---
        {
            int i = tid;                   // need 384 uint4 per buffer
            if (i < 384) {
                int r  = i >> 2;
                int c8 = (i & 3) << 3;     // halves 0,8,16,24
                *reinterpret_cast<uint4*>(&Bh[r][c8]) =
                    *reinterpret_cast<const uint4*>(&WbH[(s * 96 + r) * 384 + k0 + c8]);
                *reinterpret_cast<uint4*>(&Bl[r][c8]) =
                    *reinterpret_cast<const uint4*>(&WbL[(s * 96 + r) * 384 + k0 + c8]);
            } else {
                int j  = i - 384;          // remaining 384 handled by upper half... (256 thr: split)
                (void)j;
            }
            // second wave to cover all 384 with 256 threads
            int i2 = tid + 256;
            if (i2 < 384) {
                int r  = i2 >> 2;
                int c8 = (i2 & 3) << 3;
                *reinterpret_cast<uint4*>(&Bh[r][c8]) =
                    *reinterpret_cast<const uint4*>(&WbH[(s * 96 + r) * 384 + k0 + c8]);
                *reinterpret_cast<uint4*>(&Bl[r][c8]) =
                    *reinterpret_cast<const uint4*>(&WbL[(s * 96 + r) * 384 + k0 + c8]);
            }
        }
        __syncthreads();

        // --- compute: 2 k16 steps ---
#pragma unroll
        for (int kk = 0; kk < 32; kk += 16) {
            uint32_t ah[2][4], al[2][4];
#pragma unroll
            for (int mt = 0; mt < 2; mt++) {
                const int br = m0 + mt * 16;
                ah[mt][0] = *reinterpret_cast<const uint32_t*>(&Ah[br + gid    ][kk + tg * 2    ]);
                ah[mt][1] = *reinterpret_cast<const uint32_t*>(&Ah[br + gid + 8][kk + tg * 2    ]);
                ah[mt][2] = *reinterpret_cast<const uint32_t*>(&Ah[br + gid    ][kk + tg * 2 + 8]);
                ah[mt][3] = *reinterpret_cast<const uint32_t*>(&Ah[br + gid + 8][kk + tg * 2 + 8]);
                al[mt][0] = *reinterpret_cast<const uint32_t*>(&Al[br + gid    ][kk + tg * 2    ]);
                al[mt][1] = *reinterpret_cast<const uint32_t*>(&Al[br + gid + 8][kk + tg * 2    ]);
                al[mt][2] = *reinterpret_cast<const uint32_t*>(&Al[br + gid    ][kk + tg * 2 + 8]);
                al[mt][3] = *reinterpret_cast<const uint32_t*>(&Al[br + gid + 8][kk + tg * 2 + 8]);
            }
#pragma unroll
            for (int nt = 0; nt < 6; nt++) {
                const int bn = n0 + nt * 8 + gid;
                uint32_t bh0 = *reinterpret_cast<const uint32_t*>(&Bh[bn][kk + tg * 2    ]);
                uint32_t bh1 = *reinterpret_cast<const uint32_t*>(&Bh[bn][kk + tg * 2 + 8]);
                uint32_t bl0 = *reinterpret_cast<const uint32_t*>(&Bl[bn][kk + tg * 2    ]);
                uint32_t bl1 = *reinterpret_cast<const uint32_t*>(&Bl[bn][kk + tg * 2 + 8]);
#pragma unroll
                for (int mt = 0; mt < 2; mt++) {
                    float* cc = acc[mt][nt];
                    mma16816(cc[0], cc[1], cc[2], cc[3],
                             ah[mt][0], ah[mt][1], ah[mt][2], ah[mt][3], bh0, bh1);
                    mma16816(cc[0], cc[1], cc[2], cc[3],
                             ah[mt][0], ah[mt][1], ah[mt][2], ah[mt][3], bl0, bl1);
                    mma16816(cc[0], cc[1], cc[2], cc[3],
                             al[mt][0], al[mt][1], al[mt][2], al[mt][3], bh0, bh1);
                }
            }
        }
    }

    // --- epilogue: scatter fp32 results to Qg/Kg/Vg ---
#pragma unroll
    for (int nt = 0; nt < 6; nt++) {
        const int col_g0 = s * 96 + n0 + nt * 8;
        const int mat    = col_g0 >> 6;
        const int hs0    = (col_g0 & 63) + tg * 2;
        float* dst = (mat == 0) ? Qg : ((mat == 1) ? Kg : Vg);
#pragma unroll
        for (int mt = 0; mt < 2; mt++) {
            const size_t rowA = row0 + m0 + mt * 16 + gid;
            const size_t rowB = rowA + 8;
            *reinterpret_cast<float2*>(&dst[rowA * HS + hs0]) =
                make_float2(acc[mt][nt][0], acc[mt][nt][1]);
            *reinterpret_cast<float2*>(&dst[rowB * HS + hs0]) =
                make_float2(acc[mt][nt][2], acc[mt][nt][3]);
        }
    }
}

// ============================================================================
// Kernel 2: fused causal attention, thread-per-query, K/V chunked in 64-row
// tiles (32 KB static smem -> 2 CTAs/SM). 2-key unroll, FMA-pipe softmax.
// ============================================================================
__global__ __launch_bounds__(128, 2)
void attn_kernel(float* __restrict__ out)
{
    __shared__ float Ks[64 * HS];
    __shared__ float Vs[64 * HS];

    const int half = blockIdx.x;
    const int b    = blockIdx.y;
    const int tid  = threadIdx.x;
    const int qrow = half * 128 + tid;
    const int kend = qrow + 1;
    const int nchunks = (half + 1) * 2;

    const float* Kb = Kg + (size_t)b * TT * HS;
    const float* Vb = Vg + (size_t)b * TT * HS;

    const float* qptr = Qg + ((size_t)b * TT + qrow) * HS;
    ull q2[32];
#pragma unroll
    for (int i = 0; i < 16; i++) {
        float4 v = *reinterpret_cast<const float4*>(qptr + 4 * i);
        q2[2 * i]     = pack2(v.x, v.y);
        q2[2 * i + 1] = pack2(v.z, v.w);
    }

    float m = -1e30f, l = 0.f;
    ull acc2[32];
#pragma unroll
    for (int d = 0; d < 32; d++) acc2[d] = pack2(0.f, 0.f);

    for (int c = 0; c < nchunks; c++) {
        __syncthreads();
        {
            const float4* sk = reinterpret_cast<const float4*>(Kb + c * 64 * HS);
            const float4* sv = reinterpret_cast<const float4*>(Vb + c * 64 * HS);
#pragma unroll
            for (int it = 0; it < 8; it++) {
                int i = tid + 128 * it;
                reinterpret_cast<float4*>(Ks)[i] = sk[i];
                reinterpret_cast<float4*>(Vs)[i] = sv[i];
            }
        }
        __syncthreads();

        int nk = kend - c * 64;
        if (nk > 64) nk = 64;
        int j = 0;
        for (; j + 2 <= nk; j += 2) {
            const ulonglong2* ka  = reinterpret_cast<const ulonglong2*>(Ks + j * HS);
            const ulonglong2* kb2 = reinterpret_cast<const ulonglong2*>(Ks + (j + 1) * HS);
            ull sa[2], sb2[2];
            sa[0] = sa[1] = sb2[0] = sb2[1] = pack2(0.f, 0.f);
#pragma unroll
            for (int d = 0; d < 16; d++) {
                ulonglong2 kva = ka[d];
                ulonglong2 kvb = kb2[d];
                sa[0]  = fma2(q2[2 * d],     kva.x, sa[0]);
                sa[1]  = fma2(q2[2 * d + 1], kva.y, sa[1]);
                sb2[0] = fma2(q2[2 * d],     kvb.x, sb2[0]);
                sb2[1] = fma2(q2[2 * d + 1], kvb.y, sb2[1]);
            }
            float a0, a1, a2v, a3;
            unpack2(add2(sa[0], sa[1]), a0, a1);
            unpack2(add2(sb2[0], sb2[1]), a2v, a3);
            float s0 = (a0 + a1) * 0.125f;
            float s1 = (a2v + a3) * 0.125f;

            const float mn = fmaxf(m, fmaxf(s0, s1));
            if (mn > m) {
                const float corr = fexp(m - mn);
                l *= corr;
                const ull c2 = pack2(corr, corr);
#pragma unroll
                for (int d = 0; d < 32; d++) acc2[d] = mul2(acc2[d], c2);
                m = mn;
            }
            const float p0 = fexp(s0 - m);
            const float p1 = fexp(s1 - m);
            l += p0 + p1;

            const ull p02 = pack2(p0, p0);
            const ull p12 = pack2(p1, p1);
            const ulonglong2* va  = reinterpret_cast<const ulonglong2*>(Vs + j * HS);
            const ulonglong2* vb2 = reinterpret_cast<const ulonglong2*>(Vs + (j + 1) * HS);
#pragma unroll
            for (int d = 0; d < 16; d++) {
                ulonglong2 v0 = va[d];
                ulonglong2 v1 = vb2[d];
                acc2[2 * d]     = fma2(p02, v0.x, acc2[2 * d]);
                acc2[2 * d + 1] = fma2(p02, v0.y, acc2[2 * d + 1]);
                acc2[2 * d]     = fma2(p12, v1.x, acc2[2 * d]);
                acc2[2 * d + 1] = fma2(p12, v1.y, acc2[2 * d + 1]);
            }
        }
        if (j < nk) {
            const ulonglong2* krow = reinterpret_cast<const ulonglong2*>(Ks + j * HS);
            ull s2[2];
            s2[0] = s2[1] = pack2(0.f, 0.f);
#pragma unroll
            for (int d = 0; d < 16; d++) {
                ulonglong2 kv = krow[d];
                s2[0] = fma2(q2[2 * d],     kv.x, s2[0]);
                s2[1] = fma2(q2[2 * d + 1], kv.y, s2[1]);
            }
            float a0, a1;
            unpack2(add2(s2[0], s2[1]), a0, a1);
            float s = (a0 + a1) * 0.125f;
            const float mn = fmaxf(m, s);
            if (mn > m) {
                const float corr = fexp(m - mn);
                l *= corr;
                const ull c2 = pack2(corr, corr);
#pragma unroll
                for (int d = 0; d < 32; d++) acc2[d] = mul2(acc2[d], c2);
                m = mn;
            }
            const float p = fexp(s - m);
            l += p;
            const ull p2 = pack2(p, p);
            const ulonglong2* vrow = reinterpret_cast<const ulonglong2*>(Vs + j * HS);
#pragma unroll
            for (int d = 0; d < 16; d++) {
                ulonglong2 vv = vrow[d];
                acc2[2 * d]     = fma2(p2, vv.x, acc2[2 * d]);
                acc2[2 * d + 1] = fma2(p2, vv.y, acc2[2 * d + 1]);
            }
        }
    }

    const float inv = 1.f / l;
    float* optr = out + ((size_t)b * TT + qrow) * HS;
#pragma unroll
    for (int i = 0; i < 16; i++) {
        float l0, h0, l1, h1;
        unpack2(acc2[2 * i],     l0, h0);
        unpack2(acc2[2 * i + 1], l1, h1);
        *reinterpret_cast<float4*>(optr + 4 * i) =
            make_float4(l0 * inv, h0 * inv, l1 * inv, h1 * inv);
    }
}

// ============================================================================
extern "C" void kernel_launch(void* const* d_in, const int* in_sizes, int n_in,
                              void* d_out, int out_size)
{
    const float* x  = (const float*)d_in[0];
    const float* Wq = (const float*)d_in[1];
    const float* Wk = (const float*)d_in[2];
    const float* Wv = (const float*)d_in[3];
    float* out = (float*)d_out;

    (void)in_sizes; (void)n_in; (void)out_size;

    // 0) split W into bf16 hi/lo
    prep_w<<<(192 * 384 + 255) / 256, 256>>>(Wq, Wk, Wv);

    // 1) QKV projection on tensor cores (mma.sync bf16, 3-pass split)
    dim3 qgrid(2048, 2);
    qkv_mma<<<qgrid, 256>>>(x);

    // 2) fused causal attention
    dim3 agrid(2, BB);
    attn_kernel<<<agrid, 128>>>(out);
}

// round 4
// speedup vs baseline: 2.6569x; 1.5875x over previous
#include <cuda_runtime.h>
#include <cuda_bf16.h>
#include <cstdint>

#define BB   1024
#define TT   256
#define CC   384
#define HS   64

// Scratch (device globals: allocation-free).
__device__ float Qg[BB * TT * HS];
__device__ float Kg[BB * TT * HS];
__device__ float Vtg[BB * HS * TT];   // V transposed: [b][hs][t]

// Pre-split W, bf16 hi/lo, layout [n=192][k=384] (n = m*64 + hs), k-contiguous.
__device__ __align__(16) __nv_bfloat16 WbH[192 * 384];
__device__ __align__(16) __nv_bfloat16 WbL[192 * 384];

// ---------------- helpers ----------------
__device__ __forceinline__ uint32_t smem_u32(const void* p) {
    uint32_t a;
    asm("{ .reg .u64 t; cvta.to.shared.u64 t, %1; cvt.u32.u64 %0, t; }" : "=r"(a) : "l"(p));
    return a;
}
__device__ __forceinline__ void cp16(uint32_t dst, const void* src) {
    asm volatile("cp.async.ca.shared.global [%0], [%1], 16;" :: "r"(dst), "l"(src) : "memory");
}
#define CP_COMMIT() asm volatile("cp.async.commit_group;" ::: "memory")
#define CP_WAIT1()  asm volatile("cp.async.wait_group 1;" ::: "memory")
#define CP_WAIT0()  asm volatile("cp.async.wait_group 0;" ::: "memory")

// fp32 -> bf16 hi/lo split of a pair, packed for mma (low half = first element).
__device__ __forceinline__ void split2(float a, float b, uint32_t& h, uint32_t& l) {
    __nv_bfloat162 hh = __floats2bfloat162_rn(a, b);
    float ra = a - __bfloat162float(hh.x);
    float rb = b - __bfloat162float(hh.y);
    __nv_bfloat162 ll = __floats2bfloat162_rn(ra, rb);
    h = *reinterpret_cast<uint32_t*>(&hh);
    l = *reinterpret_cast<uint32_t*>(&ll);
}

// exp2(x) for x <= 0, FMA pipe only.
__device__ __forceinline__ float fexp2f(float x) {
    x = fmaxf(x, -125.0f);
    float fi = floorf(x);
    float f = x - fi;
    float p = 0.0018775767f;
    p = fmaf(p, f, 0.0089893397f);
    p = fmaf(p, f, 0.055826318f);
    p = fmaf(p, f, 0.24015361f);
    p = fmaf(p, f, 0.69315308f);
    p = fmaf(p, f, 1.0f);
    return p * __int_as_float(((int)fi + 127) << 23);
}
#define SCALE2 0.18033688f   // 0.125 * log2(e)

__device__ __forceinline__ void mma16816(float& c0, float& c1, float& c2, float& c3,
                                         uint32_t a0, uint32_t a1, uint32_t a2, uint32_t a3,
                                         uint32_t b0, uint32_t b1) {
    asm volatile(
        "mma.sync.aligned.m16n8k16.row.col.f32.bf16.bf16.f32 "
        "{%0,%1,%2,%3}, {%4,%5,%6,%7}, {%8,%9}, {%0,%1,%2,%3};"
        : "+f"(c0), "+f"(c1), "+f"(c2), "+f"(c3)
        : "r"(a0), "r"(a1), "r"(a2), "r"(a3), "r"(b0), "r"(b1));
}

// ============================================================================
// Kernel 0: split W into bf16 hi/lo at layout [n][k].
// ============================================================================
__global__ void prep_w(const float* __restrict__ Wq,
                       const float* __restrict__ Wk,
                       const float* __restrict__ Wv)
{
    int idx = blockIdx.x * blockDim.x + threadIdx.x;
    if (idx >= 192 * 384) return;
    int n = idx / 384;
    int k = idx % 384;
    int m = n >> 6, hs = n & 63;
    const float* W = (m == 0) ? Wq : ((m == 1) ? Wk : Wv);
    float v = W[k * HS + hs];
    __nv_bfloat16 h = __float2bfloat16(v);
    __nv_bfloat16 l = __float2bfloat16(v - __bfloat162float(h));
    WbH[n * 384 + k] = h;
    WbL[n * 384 + k] = l;
}

// ============================================================================
// Kernel 1: QKV projection, cp.async double-buffered, split at fragment load.
// Grid (2048, 2), 256 thr. CTA tile 128(M) x 96(N). 8 warps 4m x 2n (32x48).
// ============================================================================
#define XP 36
#define BP 40
#define XS_BYTES (128 * XP * 4)     // 18432
#define B_BYTES  (96 * BP * 2)      // 7680
#define OFF_X(b)  ((b) * XS_BYTES)
#define OFF_BH(b) (2 * XS_BYTES + (b) * B_BYTES)
#define OFF_BL(b) (2 * XS_BYTES + 2 * B_BYTES + (b) * B_BYTES)
#define QKV_SMEM  (2 * XS_BYTES + 4 * B_BYTES)   // 67584

__global__ __launch_bounds__(256, 2)
void qkv_mma(const float* __restrict__ X)
{
    extern __shared__ char sm[];
    const uint32_t sb = smem_u32(sm);
    const int tid  = threadIdx.x;
    const int lane = tid & 31;
    const int w    = tid >> 5;
    const int m0   = (w >> 1) * 32;
    const int n0   = (w & 1) * 48;
    const int gid  = lane >> 2;
    const int tg   = lane & 3;
    const size_t row0 = (size_t)blockIdx.x * 128;
    const int    s    = blockIdx.y;

    auto stage = [&](int c, int buf) {
        const int k0 = c * 32;
#pragma unroll
        for (int it = 0; it < 4; it++) {
            int i  = tid + 256 * it;
            int r  = i >> 3;
            int c4 = (i & 7) << 2;
            cp16(sb + OFF_X(buf) + (uint32_t)(r * XP + c4) * 4,
                 &X[(row0 + r) * CC + k0 + c4]);
        }
        {
            int i = tid;
            if (i < 384) {
                int r = i >> 2, c8 = (i & 3) << 3;
                cp16(sb + OFF_BH(buf) + (uint32_t)(r * BP + c8) * 2,
                     &WbH[(size_t)(s * 96 + r) * 384 + k0 + c8]);
                cp16(sb + OFF_BL(buf) + (uint32_t)(r * BP + c8) * 2,
                     &WbL[(size_t)(s * 96 + r) * 384 + k0 + c8]);
            }
            int i2 = tid + 256;
            if (i2 < 384) {
                int r = i2 >> 2, c8 = (i2 & 3) << 3;
                cp16(sb + OFF_BH(buf) + (uint32_t)(r * BP + c8) * 2,
                     &WbH[(size_t)(s * 96 + r) * 384 + k0 + c8]);
                cp16(sb + OFF_BL(buf) + (uint32_t)(r * BP + c8) * 2,
                     &WbL[(size_t)(s * 96 + r) * 384 + k0 + c8]);
            }
        }
        CP_COMMIT();
    };

    float acc[2][6][4] = {};

    stage(0, 0);
#pragma unroll 1
    for (int c = 0; c < 12; c++) {
        if (c < 11) { stage(c + 1, (c + 1) & 1); CP_WAIT1(); } else { CP_WAIT0(); }
        __syncthreads();
        const int buf = c & 1;
        const float* Xb = reinterpret_cast<const float*>(sm + OFF_X(buf));
        const __nv_bfloat16* Bh = reinterpret_cast<const __nv_bfloat16*>(sm + OFF_BH(buf));
        const __nv_bfloat16* Bl = reinterpret_cast<const __nv_bfloat16*>(sm + OFF_BL(buf));
#pragma unroll
        for (int kk = 0; kk < 32; kk += 16) {
            uint32_t ah[2][4], al[2][4];
#pragma unroll
            for (int mt = 0; mt < 2; mt++) {
                const int r0 = m0 + mt * 16 + gid;
                float2 x0 = *reinterpret_cast<const float2*>(&Xb[r0 * XP + kk + 2 * tg]);
                float2 x1 = *reinterpret_cast<const float2*>(&Xb[(r0 + 8) * XP + kk + 2 * tg]);
                float2 x2 = *reinterpret_cast<const float2*>(&Xb[r0 * XP + kk + 2 * tg + 8]);
                float2 x3 = *reinterpret_cast<const float2*>(&Xb[(r0 + 8) * XP + kk + 2 * tg + 8]);
                split2(x0.x, x0.y, ah[mt][0], al[mt][0]);
                split2(x1.x, x1.y, ah[mt][1], al[mt][1]);
                split2(x2.x, x2.y, ah[mt][2], al[mt][2]);
                split2(x3.x, x3.y, ah[mt][3], al[mt][3]);
            }
#pragma unroll
            for (int nt = 0; nt < 6; nt++) {
                const int bn = n0 + nt * 8 + gid;
                uint32_t bh0 = *reinterpret_cast<const uint32_t*>(&Bh[bn * BP + kk + 2 * tg]);
                uint32_t bh1 = *reinterpret_cast<const uint32_t*>(&Bh[bn * BP + kk + 2 * tg + 8]);
                uint32_t bl0 = *reinterpret_cast<const uint32_t*>(&Bl[bn * BP + kk + 2 * tg]);
                uint32_t bl1 = *reinterpret_cast<const uint32_t*>(&Bl[bn * BP + kk + 2 * tg + 8]);
#pragma unroll
                for (int mt = 0; mt < 2; mt++) {
                    float* cc = acc[mt][nt];
                    mma16816(cc[0], cc[1], cc[2], cc[3],
                             ah[mt][0], ah[mt][1], ah[mt][2], ah[mt][3], bh0, bh1);
                    mma16816(cc[0], cc[1], cc[2], cc[3],
                             ah[mt][0], ah[mt][1], ah[mt][2], ah[mt][3], bl0, bl1);
                    mma16816(cc[0], cc[1], cc[2], cc[3],
                             al[mt][0], al[mt][1], al[mt][2], al[mt][3], bh0, bh1);
                }
            }
        }
        __syncthreads();
    }

    // epilogue
#pragma unroll
    for (int nt = 0; nt < 6; nt++) {
        const int colg = s * 96 + n0 + nt * 8 + 2 * tg;
        const int mat  = colg >> 6;
        const int hs0  = colg & 63;
#pragma unroll
        for (int mt = 0; mt < 2; mt++) {
            const size_t rowA = row0 + m0 + mt * 16 + gid;
            const size_t rowB = rowA + 8;
            const float* cc = acc[mt][nt];
            if (mat == 2) {
                // V transposed: Vtg[b][hs][t]
                const size_t baseA = (rowA >> 8) * (size_t)(HS * TT) + (rowA & 255);
                const size_t baseB = (rowB >> 8) * (size_t)(HS * TT) + (rowB & 255);
                Vtg[baseA + (size_t)hs0 * TT]       = cc[0];
                Vtg[baseA + (size_t)(hs0 + 1) * TT] = cc[1];
                Vtg[baseB + (size_t)hs0 * TT]       = cc[2];
                Vtg[baseB + (size_t)(hs0 + 1) * TT] = cc[3];
            } else {
                float* dst = (mat == 0) ? Qg : Kg;
                *reinterpret_cast<float2*>(&dst[rowA * HS + hs0]) = make_float2(cc[0], cc[1]);
                *reinterpret_cast<float2*>(&dst[rowB * HS + hs0]) = make_float2(cc[2], cc[3]);
            }
        }
    }
}

// ============================================================================
// Kernel 2: FA2-style causal attention on mma.sync, split-bf16 3-pass.
// Grid (2, 1024), 256 thr = 8 warps x 16 query rows. 64-key chunks.
// ============================================================================
#define KP 72

__global__ __launch_bounds__(256)
void attn_mma(float* __restrict__ out)
{
    __shared__ __nv_bfloat16 Khs[64][KP], Kls[64][KP];
    __shared__ __nv_bfloat16 Vhs[64][KP], Vls[64][KP];

    const int half = blockIdx.x;
    const int b    = blockIdx.y;
    const int tid  = threadIdx.x;
    const int lane = tid & 31;
    const int w    = tid >> 5;
    const int gid  = lane >> 2;
    const int tg   = lane & 3;
    const int qb   = half * 128 + w * 16;

    // Q fragments (fp32 -> split bf16), rows qb+gid, qb+8+gid
    uint32_t qh[4][4], ql[4][4];
    {
        const float* q0 = Qg + ((size_t)b * TT + qb + gid) * HS;
        const float* q1 = q0 + 8 * HS;
#pragma unroll
        for (int ks = 0; ks < 4; ks++) {
            float2 v0 = *reinterpret_cast<const float2*>(&q0[ks * 16 + 2 * tg]);
            float2 v1 = *reinterpret_cast<const float2*>(&q1[ks * 16 + 2 * tg]);
            float2 v2 = *reinterpret_cast<const float2*>(&q0[ks * 16 + 2 * tg + 8]);
            float2 v3 = *reinterpret_cast<const float2*>(&q1[ks * 16 + 2 * tg + 8]);
            split2(v0.x, v0.y, qh[ks][0], ql[ks][0]);
            split2(v1.x, v1.y, qh[ks][1], ql[ks][1]);
            split2(v2.x, v2.y, qh[ks][2], ql[ks][2]);
            split2(v3.x, v3.y, qh[ks][3], ql[ks][3]);
        }
    }

    float O[32];
#pragma unroll
    for (int i = 0; i < 32; i++) O[i] = 0.f;
    float mr0 = -1e30f, mr1 = -1e30f, l0 = 0.f, l1 = 0.f;

    const int nch = (half + 1) * 2;
#pragma unroll 1
    for (int c = 0; c < nch; c++) {
        const int kn0 = c * 64;
        __syncthreads();
        // stage K[key][hs] and Vt[hs][key], split to bf16 hi/lo
#pragma unroll
        for (int it = 0; it < 4; it++) {
            int i  = tid + 256 * it;
            int r  = i >> 4;
            int c4 = (i & 15) << 2;
            float4 kv = *reinterpret_cast<const float4*>(
                &Kg[((size_t)b * TT + kn0 + r) * HS + c4]);
            uint32_t h0, lo0, h1, lo1;
            split2(kv.x, kv.y, h0, lo0);
            split2(kv.z, kv.w, h1, lo1);
            *reinterpret_cast<uint2*>(&Khs[r][c4]) = make_uint2(h0, h1);
            *reinterpret_cast<uint2*>(&Kls[r][c4]) = make_uint2(lo0, lo1);
            float4 vv = *reinterpret_cast<const float4*>(
                &Vtg[((size_t)b * HS + r) * TT + kn0 + c4]);
            split2(vv.x, vv.y, h0, lo0);
            split2(vv.z, vv.w, h1, lo1);
            *reinterpret_cast<uint2*>(&Vhs[r][c4]) = make_uint2(h0, h1);
            *reinterpret_cast<uint2*>(&Vls[r][c4]) = make_uint2(lo0, lo1);
        }
        __syncthreads();
        if (kn0 > qb) continue;   // warp-uniform causal skip

        // ---- scores: S = Q K^T (3-pass split) ----
        float s[32];
#pragma unroll
        for (int nt = 0; nt < 8; nt++) {
            float c0 = 0.f, c1 = 0.f, c2 = 0.f, c3 = 0.f;
            const int bn = nt * 8 + gid;
#pragma unroll
            for (int ks = 0; ks < 4; ks++) {
                uint32_t bh0 = *reinterpret_cast<const uint32_t*>(&Khs[bn][ks * 16 + 2 * tg]);
                uint32_t bh1 = *reinterpret_cast<const uint32_t*>(&Khs[bn][ks * 16 + 2 * tg + 8]);
                uint32_t bl0 = *reinterpret_cast<const uint32_t*>(&Kls[bn][ks * 16 + 2 * tg]);
                uint32_t bl1 = *reinterpret_cast<const uint32_t*>(&Kls[bn][ks * 16 + 2 * tg + 8]);
                mma16816(c0, c1, c2, c3, qh[ks][0], qh[ks][1], qh[ks][2], qh[ks][3], bh0, bh1);
                mma16816(c0, c1, c2, c3, qh[ks][0], qh[ks][1], qh[ks][2], qh[ks][3], bl0, bl1);
                mma16816(c0, c1, c2, c3, ql[ks][0], ql[ks][1], ql[ks][2], ql[ks][3], bh0, bh1);
            }
            s[nt * 4 + 0] = c0 * SCALE2;
            s[nt * 4 + 1] = c1 * SCALE2;
            s[nt * 4 + 2] = c2 * SCALE2;
            s[nt * 4 + 3] = c3 * SCALE2;
        }
        // causal mask (diagonal chunk only)
        if (kn0 + 63 > qb) {
            const int r0 = qb + gid, r1 = qb + 8 + gid;
#pragma unroll
            for (int nt = 0; nt < 8; nt++) {
                const int col = kn0 + nt * 8 + 2 * tg;
                if (col     > r0) s[nt * 4 + 0] = -1e30f;
                if (col + 1 > r0) s[nt * 4 + 1] = -1e30f;
                if (col     > r1) s[nt * 4 + 2] = -1e30f;
                if (col + 1 > r1) s[nt * 4 + 3] = -1e30f;
            }
        }
        // ---- online softmax (base-2) ----
        float c0m = -1e30f, c1m = -1e30f;
#pragma unroll
        for (int nt = 0; nt < 8; nt++) {
            c0m = fmaxf(c0m, fmaxf(s[nt * 4 + 0], s[nt * 4 + 1]));
            c1m = fmaxf(c1m, fmaxf(s[nt * 4 + 2], s[nt * 4 + 3]));
        }
        c0m = fmaxf(c0m, __shfl_xor_sync(0xffffffffu, c0m, 1));
        c0m = fmaxf(c0m, __shfl_xor_sync(0xffffffffu, c0m, 2));
        c1m = fmaxf(c1m, __shfl_xor_sync(0xffffffffu, c1m, 1));
        c1m = fmaxf(c1m, __shfl_xor_sync(0xffffffffu, c1m, 2));
        const float mn0 = fmaxf(mr0, c0m), mn1 = fmaxf(mr1, c1m);
        const float corr0 = fexp2f(mr0 - mn0), corr1 = fexp2f(mr1 - mn1);
        mr0 = mn0; mr1 = mn1;

        float sum0 = 0.f, sum1 = 0.f;
#pragma unroll
        for (int nt = 0; nt < 8; nt++) {
            float p0 = fexp2f(s[nt * 4 + 0] - mn0);
            float p1 = fexp2f(s[nt * 4 + 1] - mn0);
            float p2 = fexp2f(s[nt * 4 + 2] - mn1);
            float p3 = fexp2f(s[nt * 4 + 3] - mn1);
            s[nt * 4 + 0] = p0; s[nt * 4 + 1] = p1;
            s[nt * 4 + 2] = p2; s[nt * 4 + 3] = p3;
            sum0 += p0 + p1; sum1 += p2 + p3;
        }
        sum0 += __shfl_xor_sync(0xffffffffu, sum0, 1);
        sum0 += __shfl_xor_sync(0xffffffffu, sum0, 2);
        sum1 += __shfl_xor_sync(0xffffffffu, sum1, 1);
        sum1 += __shfl_xor_sync(0xffffffffu, sum1, 2);
        l0 = l0 * corr0 + sum0;
        l1 = l1 * corr1 + sum1;
#pragma unroll
        for (int hn = 0; hn < 8; hn++) {
            O[hn * 4 + 0] *= corr0; O[hn * 4 + 1] *= corr0;
            O[hn * 4 + 2] *= corr1; O[hn * 4 + 3] *= corr1;
        }
        // ---- PV: O += P V (P fragments reuse score registers; 3-pass) ----
#pragma unroll
        for (int ks = 0; ks < 4; ks++) {
            uint32_t ph[4], pl[4];
            split2(s[(2 * ks) * 4 + 0],     s[(2 * ks) * 4 + 1],     ph[0], pl[0]);
            split2(s[(2 * ks) * 4 + 2],     s[(2 * ks) * 4 + 3],     ph[1], pl[1]);
            split2(s[(2 * ks + 1) * 4 + 0], s[(2 * ks + 1) * 4 + 1], ph[2], pl[2]);
            split2(s[(2 * ks + 1) * 4 + 2], s[(2 * ks + 1) * 4 + 3], ph[3], pl[3]);
#pragma unroll
            for (int hn = 0; hn < 8; hn++) {
                const int vn = hn * 8 + gid;
                uint32_t vh0 = *reinterpret_cast<const uint32_t*>(&Vhs[vn][ks * 16 + 2 * tg]);
                uint32_t vh1 = *reinterpret_cast<const uint32_t*>(&Vhs[vn][ks * 16 + 2 * tg + 8]);
                uint32_t vl0 = *reinterpret_cast<const uint32_t*>(&Vls[vn][ks * 16 + 2 * tg]);
                uint32_t vl1 = *reinterpret_cast<const uint32_t*>(&Vls[vn][ks * 16 + 2 * tg + 8]);
                float* o = &O[hn * 4];
                mma16816(o[0], o[1], o[2], o[3], ph[0], ph[1], ph[2], ph[3], vh0, vh1);
                mma16816(o[0], o[1], o[2], o[3], pl[0], pl[1], pl[2], pl[3], vh0, vh1);
                mma16816(o[0], o[1], o[2], o[3], ph[0], ph[1], ph[2], ph[3], vl0, vl1);
            }
        }
    }

    const float i0 = 1.f / l0, i1 = 1.f / l1;
    float* o0 = out + ((size_t)b * TT + qb + gid) * HS;
    float* o1 = o0 + 8 * HS;
#pragma unroll
    for (int hn = 0; hn < 8; hn++) {
        *reinterpret_cast<float2*>(&o0[hn * 8 + 2 * tg]) =
            make_float2(O[hn * 4 + 0] * i0, O[hn * 4 + 1] * i0);
        *reinterpret_cast<float2*>(&o1[hn * 8 + 2 * tg]) =
            make_float2(O[hn * 4 + 2] * i1, O[hn * 4 + 3] * i1);
    }
}

// ============================================================================
extern "C" void kernel_launch(void* const* d_in, const int* in_sizes, int n_in,
                              void* d_out, int out_size)
{
    const float* x  = (const float*)d_in[0];
    const float* Wq = (const float*)d_in[1];
    const float* Wk = (const float*)d_in[2];
    const float* Wv = (const float*)d_in[3];
    float* out = (float*)d_out;

    (void)in_sizes; (void)n_in; (void)out_size;

    prep_w<<<(192 * 384 + 255) / 256, 256>>>(Wq, Wk, Wv);

    cudaFuncSetAttribute(qkv_mma, cudaFuncAttributeMaxDynamicSharedMemorySize, QKV_SMEM);
    dim3 qgrid(2048, 2);
    qkv_mma<<<qgrid, 256, QKV_SMEM>>>(x);

    dim3 agrid(2, BB);
    attn_mma<<<agrid, 256>>>(out);
}

// round 5
// speedup vs baseline: 2.7842x; 1.0479x over previous
#include <cuda_runtime.h>
#include <cuda_bf16.h>
#include <cstdint>

#define BB   1024
#define TT   256
#define CC   384
#define HS   64

// Pre-split scratch (device globals: allocation-free).
__device__ __align__(16) __nv_bfloat16 QhG[BB * TT * HS], QlG[BB * TT * HS];
__device__ __align__(16) __nv_bfloat16 KhG[BB * TT * HS], KlG[BB * TT * HS];
__device__ __align__(16) __nv_bfloat16 VthG[BB * HS * TT], VtlG[BB * HS * TT]; // [b][hs][t]
__device__ __align__(16) __nv_bfloat16 WbH[192 * 384], WbL[192 * 384];         // [n][k]

// ---------------- helpers ----------------
__device__ __forceinline__ uint32_t smem_u32(const void* p) {
    uint32_t a;
    asm("{ .reg .u64 t; cvta.to.shared.u64 t, %1; cvt.u32.u64 %0, t; }" : "=r"(a) : "l"(p));
    return a;
}
__device__ __forceinline__ void cp16(uint32_t dst, const void* src) {
    asm volatile("cp.async.ca.shared.global [%0], [%1], 16;" :: "r"(dst), "l"(src) : "memory");
}
#define CP_COMMIT() asm volatile("cp.async.commit_group;" ::: "memory")
#define CP_WAIT1()  asm volatile("cp.async.wait_group 1;" ::: "memory")
#define CP_WAIT0()  asm volatile("cp.async.wait_group 0;" ::: "memory")

// fp32 pair -> packed bf16 hi / lo pair.
__device__ __forceinline__ void split2(float a, float b, uint32_t& h, uint32_t& l) {
    __nv_bfloat162 hh = __floats2bfloat162_rn(a, b);
    float ra = a - __bfloat162float(hh.x);
    float rb = b - __bfloat162float(hh.y);
    __nv_bfloat162 ll = __floats2bfloat162_rn(ra, rb);
    h = *reinterpret_cast<uint32_t*>(&hh);
    l = *reinterpret_cast<uint32_t*>(&ll);
}

// exp2(x) for x <= 0, FMA pipe only.
__device__ __forceinline__ float fexp2f(float x) {
    x = fmaxf(x, -125.0f);
    float fi = floorf(x);
    float f = x - fi;
    float p = 0.0018775767f;
    p = fmaf(p, f, 0.0089893397f);
    p = fmaf(p, f, 0.055826318f);
    p = fmaf(p, f, 0.24015361f);
    p = fmaf(p, f, 0.69315308f);
    p = fmaf(p, f, 1.0f);
    return p * __int_as_float(((int)fi + 127) << 23);
}
#define SCALE2 0.18033688f   // 0.125 * log2(e)

__device__ __forceinline__ void mma16816(float& c0, float& c1, float& c2, float& c3,
                                         uint32_t a0, uint32_t a1, uint32_t a2, uint32_t a3,
                                         uint32_t b0, uint32_t b1) {
    asm volatile(
        "mma.sync.aligned.m16n8k16.row.col.f32.bf16.bf16.f32 "
        "{%0,%1,%2,%3}, {%4,%5,%6,%7}, {%8,%9}, {%0,%1,%2,%3};"
        : "+f"(c0), "+f"(c1), "+f"(c2), "+f"(c3)
        : "r"(a0), "r"(a1), "r"(a2), "r"(a3), "r"(b0), "r"(b1));
}

// ============================================================================
// Kernel 0: split W into bf16 hi/lo at layout [n][k].
// ============================================================================
__global__ void prep_w(const float* __restrict__ Wq,
                       const float* __restrict__ Wk,
                       const float* __restrict__ Wv)
{
    int idx = blockIdx.x * blockDim.x + threadIdx.x;
    if (idx >= 192 * 384) return;
    int n = idx / 384;
    int k = idx % 384;
    int m = n >> 6, hs = n & 63;
    const float* W = (m == 0) ? Wq : ((m == 1) ? Wk : Wv);
    float v = W[k * HS + hs];
    __nv_bfloat16 h = __float2bfloat16(v);
    __nv_bfloat16 l = __float2bfloat16(v - __bfloat162float(h));
    WbH[n * 384 + k] = h;
    WbL[n * 384 + k] = l;
}

// ============================================================================
// Kernel 1: QKV projection, merged N=192, cp.async double-buffered.
// Grid 2048, 256 thr. CTA tile 128(M) x 192(N). 8 warps 4m x 2n (32x96).
// Epilogue stores pre-split bf16 Q/K (row-major) and V (transposed).
// ============================================================================
#define XP 36
#define BP 40
#define XBYTES (128 * XP * 4)      // 18432
#define BBYTES (192 * BP * 2)      // 15360
#define QBUF   (XBYTES + 2 * BBYTES)   // 49152
#define OFFX(b)  ((b) * QBUF)
#define OFFBH(b) ((b) * QBUF + XBYTES)
#define OFFBL(b) ((b) * QBUF + XBYTES + BBYTES)
#define QKV_SMEM (2 * QBUF)        // 98304

__global__ __launch_bounds__(256, 1)
void qkv_mma(const float* __restrict__ X)
{
    extern __shared__ char sm[];
    const uint32_t sb = smem_u32(sm);
    const int tid  = threadIdx.x;
    const int lane = tid & 31;
    const int w    = tid >> 5;
    const int m0   = (w >> 1) * 32;
    const int n0   = (w & 1) * 96;
    const int gid  = lane >> 2;
    const int tg   = lane & 3;
    const size_t row0 = (size_t)blockIdx.x * 128;

    auto stage = [&](int c, int buf) {
        const int k0 = c * 32;
#pragma unroll
        for (int it = 0; it < 4; it++) {
            int i  = tid + 256 * it;
            int r  = i >> 3;
            int c4 = (i & 7) << 2;
            cp16(sb + OFFX(buf) + (uint32_t)(r * XP + c4) * 4,
                 &X[(row0 + r) * CC + k0 + c4]);
        }
#pragma unroll
        for (int it = 0; it < 6; it++) {
            int i   = tid + 256 * it;          // 0..1535
            int arr = (i >= 768);
            int rem = i - (arr ? 768 : 0);
            int r   = rem >> 2;
            int c8  = (rem & 3) << 3;
            const __nv_bfloat16* src = arr ? WbL : WbH;
            uint32_t dst = sb + (arr ? OFFBL(buf) : OFFBH(buf)) + (uint32_t)(r * BP + c8) * 2;
            cp16(dst, &src[r * 384 + k0 + c8]);
        }
        CP_COMMIT();
    };

    float acc[2][12][4] = {};

    stage(0, 0);
#pragma unroll 1
    for (int c = 0; c < 12; c++) {
        if (c < 11) { stage(c + 1, (c + 1) & 1); CP_WAIT1(); } else { CP_WAIT0(); }
        __syncthreads();
        const int buf = c & 1;
        const float* Xb = reinterpret_cast<const float*>(sm + OFFX(buf));
        const __nv_bfloat16* Bh = reinterpret_cast<const __nv_bfloat16*>(sm + OFFBH(buf));
        const __nv_bfloat16* Bl = reinterpret_cast<const __nv_bfloat16*>(sm + OFFBL(buf));
#pragma unroll
        for (int kk = 0; kk < 32; kk += 16) {
            uint32_t ah[2][4], al[2][4];
#pragma unroll
            for (int mt = 0; mt < 2; mt++) {
                const int r0 = m0 + mt * 16 + gid;
                float2 x0 = *reinterpret_cast<const float2*>(&Xb[r0 * XP + kk + 2 * tg]);
                float2 x1 = *reinterpret_cast<const float2*>(&Xb[(r0 + 8) * XP + kk + 2 * tg]);
                float2 x2 = *reinterpret_cast<const float2*>(&Xb[r0 * XP + kk + 2 * tg + 8]);
                float2 x3 = *reinterpret_cast<const float2*>(&Xb[(r0 + 8) * XP + kk + 2 * tg + 8]);
                split2(x0.x, x0.y, ah[mt][0], al[mt][0]);
                split2(x1.x, x1.y, ah[mt][1], al[mt][1]);
                split2(x2.x, x2.y, ah[mt][2], al[mt][2]);
                split2(x3.x, x3.y, ah[mt][3], al[mt][3]);
            }
#pragma unroll
            for (int nt = 0; nt < 12; nt++) {
                const int bn = n0 + nt * 8 + gid;
                uint32_t bh0 = *reinterpret_cast<const uint32_t*>(&Bh[bn * BP + kk + 2 * tg]);
                uint32_t bh1 = *reinterpret_cast<const uint32_t*>(&Bh[bn * BP + kk + 2 * tg + 8]);
                uint32_t bl0 = *reinterpret_cast<const uint32_t*>(&Bl[bn * BP + kk + 2 * tg]);
                uint32_t bl1 = *reinterpret_cast<const uint32_t*>(&Bl[bn * BP + kk + 2 * tg + 8]);
#pragma unroll
                for (int mt = 0; mt < 2; mt++) {
                    float* cc = acc[mt][nt];
                    mma16816(cc[0], cc[1], cc[2], cc[3],
                             ah[mt][0], ah[mt][1], ah[mt][2], ah[mt][3], bh0, bh1);
                    mma16816(cc[0], cc[1], cc[2], cc[3],
                             ah[mt][0], ah[mt][1], ah[mt][2], ah[mt][3], bl0, bl1);
                    mma16816(cc[0], cc[1], cc[2], cc[3],
                             al[mt][0], al[mt][1], al[mt][2], al[mt][3], bh0, bh1);
                }
            }
        }
        __syncthreads();
    }

    // --- epilogue: split to bf16 hi/lo, store Q/K row-major, V transposed ---
#pragma unroll
    for (int nt = 0; nt < 12; nt++) {
        const int colg = n0 + nt * 8 + 2 * tg;
        const int mat  = colg >> 6;
        const int hs0  = colg & 63;
#pragma unroll
        for (int mt = 0; mt < 2; mt++) {
            const size_t rowA = row0 + m0 + mt * 16 + gid;
            const size_t rowB = rowA + 8;
            const float* cc = acc[mt][nt];
            if (mat == 2) {
                const size_t baseA = (rowA >> 8) * (size_t)(HS * TT) + (rowA & 255);
                const size_t baseB = (rowB >> 8) * (size_t)(HS * TT) + (rowB & 255);
#pragma unroll
                for (int e = 0; e < 4; e++) {
                    const float v = cc[e];
                    __nv_bfloat16 h = __float2bfloat16(v);
                    __nv_bfloat16 l = __float2bfloat16(v - __bfloat162float(h));
                    const size_t base = (e < 2) ? baseA : baseB;
                    const size_t off  = base + (size_t)(hs0 + (e & 1)) * TT;
                    VthG[off] = h;
                    VtlG[off] = l;
                }
            } else {
                __nv_bfloat16* dh = (mat == 0) ? QhG : KhG;
                __nv_bfloat16* dl = (mat == 0) ? QlG : KlG;
                uint32_t h, l;
                split2(cc[0], cc[1], h, l);
                *reinterpret_cast<uint32_t*>(&dh[rowA * HS + hs0]) = h;
                *reinterpret_cast<uint32_t*>(&dl[rowA * HS + hs0]) = l;
                split2(cc[2], cc[3], h, l);
                *reinterpret_cast<uint32_t*>(&dh[rowB * HS + hs0]) = h;
                *reinterpret_cast<uint32_t*>(&dl[rowB * HS + hs0]) = l;
            }
        }
    }
}

// ============================================================================
// Kernel 2: FA2 attention. Pre-split bf16 operands; staging = cp.async copies,
// double-buffered 64-key chunks. Grid (2, 1024), 256 thr = 8 warps x 16 rows.
// ============================================================================
#define KP 72
#define ABUF 36864                      // Kh|Kl|Vh|Vl, each 64*KP*2 = 9216 B
#define ATTN_SMEM (2 * ABUF)            // 73728

__global__ __launch_bounds__(256, 1)
void attn_mma(float* __restrict__ out)
{
    extern __shared__ char sm[];
    const uint32_t sb = smem_u32(sm);
    const int half = blockIdx.x;
    const int b    = blockIdx.y;
    const int tid  = threadIdx.x;
    const int lane = tid & 31;
    const int w    = tid >> 5;
    const int gid  = lane >> 2;
    const int tg   = lane & 3;
    const int qb   = half * 128 + w * 16;

    auto stage = [&](int c, int buf) {
        const int kn0 = c * 64;
#pragma unroll
        for (int it = 0; it < 8; it++) {
            int i   = tid + 256 * it;     // 0..2047
            int arr = i >> 9;              // 0..3
            int rem = i & 511;
            int r   = rem >> 3;
            int c8  = (rem & 7) << 3;
            uint32_t dst = sb + buf * ABUF + arr * 9216 + (uint32_t)(r * KP + c8) * 2;
            const __nv_bfloat16* src;
            if (arr == 0)      src = &KhG[((size_t)b * TT + kn0 + r) * HS + c8];
            else if (arr == 1) src = &KlG[((size_t)b * TT + kn0 + r) * HS + c8];
            else if (arr == 2) src = &VthG[((size_t)b * HS + r) * TT + kn0 + c8];
            else               src = &VtlG[((size_t)b * HS + r) * TT + kn0 + c8];
            cp16(dst, src);
        }
        CP_COMMIT();
    };

    // Q fragments direct from pre-split global.
    uint32_t qh[4][4], ql[4][4];
    {
        const size_t r0 = (size_t)b * TT + qb + gid;
#pragma unroll
        for (int ks = 0; ks < 4; ks++) {
            const int o = ks * 16 + 2 * tg;
            qh[ks][0] = *reinterpret_cast<const uint32_t*>(&QhG[r0 * HS + o]);
            qh[ks][1] = *reinterpret_cast<const uint32_t*>(&QhG[(r0 + 8) * HS + o]);
            qh[ks][2] = *reinterpret_cast<const uint32_t*>(&QhG[r0 * HS + o + 8]);
            qh[ks][3] = *reinterpret_cast<const uint32_t*>(&QhG[(r0 + 8) * HS + o + 8]);
            ql[ks][0] = *reinterpret_cast<const uint32_t*>(&QlG[r0 * HS + o]);
            ql[ks][1] = *reinterpret_cast<const uint32_t*>(&QlG[(r0 + 8) * HS + o]);
            ql[ks][2] = *reinterpret_cast<const uint32_t*>(&QlG[r0 * HS + o + 8]);
            ql[ks][3] = *reinterpret_cast<const uint32_t*>(&QlG[(r0 + 8) * HS + o + 8]);
        }
    }

    float O[32];
#pragma unroll
    for (int i = 0; i < 32; i++) O[i] = 0.f;
    float mr0 = -1e30f, mr1 = -1e30f, l0 = 0.f, l1 = 0.f;

    const int nch = (half + 1) * 2;
    stage(0, 0);
#pragma unroll 1
    for (int c = 0; c < nch; c++) {
        if (c < nch - 1) { stage(c + 1, (c + 1) & 1); CP_WAIT1(); } else { CP_WAIT0(); }
        __syncthreads();
        const int kn0 = c * 64;
        const int buf = c & 1;
        const __nv_bfloat16* Khs = reinterpret_cast<const __nv_bfloat16*>(sm + buf * ABUF);
        const __nv_bfloat16* Kls = reinterpret_cast<const __nv_bfloat16*>(sm + buf * ABUF + 9216);
        const __nv_bfloat16* Vhs = reinterpret_cast<const __nv_bfloat16*>(sm + buf * ABUF + 18432);
        const __nv_bfloat16* Vls = reinterpret_cast<const __nv_bfloat16*>(sm + buf * ABUF + 27648);

        if (kn0 <= qb) {
            // ---- scores ----
            float s[32];
#pragma unroll
            for (int nt = 0; nt < 8; nt++) {
                float c0 = 0.f, c1 = 0.f, c2 = 0.f, c3 = 0.f;
                const int bn = nt * 8 + gid;
#pragma unroll
                for (int ks = 0; ks < 4; ks++) {
                    uint32_t bh0 = *reinterpret_cast<const uint32_t*>(&Khs[bn * KP + ks * 16 + 2 * tg]);
                    uint32_t bh1 = *reinterpret_cast<const uint32_t*>(&Khs[bn * KP + ks * 16 + 2 * tg + 8]);
                    uint32_t bl0 = *reinterpret_cast<const uint32_t*>(&Kls[bn * KP + ks * 16 + 2 * tg]);
                    uint32_t bl1 = *reinterpret_cast<const uint32_t*>(&Kls[bn * KP + ks * 16 + 2 * tg + 8]);
                    mma16816(c0, c1, c2, c3, qh[ks][0], qh[ks][1], qh[ks][2], qh[ks][3], bh0, bh1);
                    mma16816(c0, c1, c2, c3, qh[ks][0], qh[ks][1], qh[ks][2], qh[ks][3], bl0, bl1);
                    mma16816(c0, c1, c2, c3, ql[ks][0], ql[ks][1], ql[ks][2], ql[ks][3], bh0, bh1);
                }
                s[nt * 4 + 0] = c0 * SCALE2;
                s[nt * 4 + 1] = c1 * SCALE2;
                s[nt * 4 + 2] = c2 * SCALE2;
                s[nt * 4 + 3] = c3 * SCALE2;
            }
            if (kn0 + 63 > qb) {
                const int r0 = qb + gid, r1 = qb + 8 + gid;
#pragma unroll
                for (int nt = 0; nt < 8; nt++) {
                    const int col = kn0 + nt * 8 + 2 * tg;
                    if (col     > r0) s[nt * 4 + 0] = -1e30f;
                    if (col + 1 > r0) s[nt * 4 + 1] = -1e30f;
                    if (col     > r1) s[nt * 4 + 2] = -1e30f;
                    if (col + 1 > r1) s[nt * 4 + 3] = -1e30f;
                }
            }
            // ---- online softmax (base-2) ----
            float c0m = -1e30f, c1m = -1e30f;
#pragma unroll
            for (int nt = 0; nt < 8; nt++) {
                c0m = fmaxf(c0m, fmaxf(s[nt * 4 + 0], s[nt * 4 + 1]));
                c1m = fmaxf(c1m, fmaxf(s[nt * 4 + 2], s[nt * 4 + 3]));
            }
            c0m = fmaxf(c0m, __shfl_xor_sync(0xffffffffu, c0m, 1));
            c0m = fmaxf(c0m, __shfl_xor_sync(0xffffffffu, c0m, 2));
            c1m = fmaxf(c1m, __shfl_xor_sync(0xffffffffu, c1m, 1));
            c1m = fmaxf(c1m, __shfl_xor_sync(0xffffffffu, c1m, 2));
            const float mn0 = fmaxf(mr0, c0m), mn1 = fmaxf(mr1, c1m);
            const float corr0 = fexp2f(mr0 - mn0), corr1 = fexp2f(mr1 - mn1);
            mr0 = mn0; mr1 = mn1;

            float sum0 = 0.f, sum1 = 0.f;
#pragma unroll
            for (int nt = 0; nt < 8; nt++) {
                float p0 = fexp2f(s[nt * 4 + 0] - mn0);
                float p1 = fexp2f(s[nt * 4 + 1] - mn0);
                float p2 = fexp2f(s[nt * 4 + 2] - mn1);
                float p3 = fexp2f(s[nt * 4 + 3] - mn1);
                s[nt * 4 + 0] = p0; s[nt * 4 + 1] = p1;
                s[nt * 4 + 2] = p2; s[nt * 4 + 3] = p3;
                sum0 += p0 + p1; sum1 += p2 + p3;
            }
            sum0 += __shfl_xor_sync(0xffffffffu, sum0, 1);
            sum0 += __shfl_xor_sync(0xffffffffu, sum0, 2);
            sum1 += __shfl_xor_sync(0xffffffffu, sum1, 1);
            sum1 += __shfl_xor_sync(0xffffffffu, sum1, 2);
            l0 = l0 * corr0 + sum0;
            l1 = l1 * corr1 + sum1;
#pragma unroll
            for (int hn = 0; hn < 8; hn++) {
                O[hn * 4 + 0] *= corr0; O[hn * 4 + 1] *= corr0;
                O[hn * 4 + 2] *= corr1; O[hn * 4 + 3] *= corr1;
            }
            // ---- PV ----
#pragma unroll
            for (int ks = 0; ks < 4; ks++) {
                uint32_t ph[4], pl[4];
                split2(s[(2 * ks) * 4 + 0],     s[(2 * ks) * 4 + 1],     ph[0], pl[0]);
                split2(s[(2 * ks) * 4 + 2],     s[(2 * ks) * 4 + 3],     ph[1], pl[1]);
                split2(s[(2 * ks + 1) * 4 + 0], s[(2 * ks + 1) * 4 + 1], ph[2], pl[2]);
                split2(s[(2 * ks + 1) * 4 + 2], s[(2 * ks + 1) * 4 + 3], ph[3], pl[3]);
#pragma unroll
                for (int hn = 0; hn < 8; hn++) {
                    const int vn = hn * 8 + gid;
                    uint32_t vh0 = *reinterpret_cast<const uint32_t*>(&Vhs[vn * KP + ks * 16 + 2 * tg]);
                    uint32_t vh1 = *reinterpret_cast<const uint32_t*>(&Vhs[vn * KP + ks * 16 + 2 * tg + 8]);
                    uint32_t vl0 = *reinterpret_cast<const uint32_t*>(&Vls[vn * KP + ks * 16 + 2 * tg]);
                    uint32_t vl1 = *reinterpret_cast<const uint32_t*>(&Vls[vn * KP + ks * 16 + 2 * tg + 8]);
                    float* o = &O[hn * 4];
                    mma16816(o[0], o[1], o[2], o[3], ph[0], ph[1], ph[2], ph[3], vh0, vh1);
                    mma16816(o[0], o[1], o[2], o[3], pl[0], pl[1], pl[2], pl[3], vh0, vh1);
                    mma16816(o[0], o[1], o[2], o[3], ph[0], ph[1], ph[2], ph[3], vl0, vl1);
                }
            }
        }
        __syncthreads();
    }

    const float i0 = 1.f / l0, i1 = 1.f / l1;
    float* o0 = out + ((size_t)b * TT + qb + gid) * HS;
    float* o1 = o0 + 8 * HS;
#pragma unroll
    for (int hn = 0; hn < 8; hn++) {
        *reinterpret_cast<float2*>(&o0[hn * 8 + 2 * tg]) =
            make_float2(O[hn * 4 + 0] * i0, O[hn * 4 + 1] * i0);
        *reinterpret_cast<float2*>(&o1[hn * 8 + 2 * tg]) =
            make_float2(O[hn * 4 + 2] * i1, O[hn * 4 + 3] * i1);
    }
}

// ============================================================================
extern "C" void kernel_launch(void* const* d_in, const int* in_sizes, int n_in,
                              void* d_out, int out_size)
{
    const float* x  = (const float*)d_in[0];
    const float* Wq = (const float*)d_in[1];
    const float* Wk = (const float*)d_in[2];
    const float* Wv = (const float*)d_in[3];
    float* out = (float*)d_out;

    (void)in_sizes; (void)n_in; (void)out_size;

    prep_w<<<(192 * 384 + 255) / 256, 256>>>(Wq, Wk, Wv);

    cudaFuncSetAttribute(qkv_mma, cudaFuncAttributeMaxDynamicSharedMemorySize, QKV_SMEM);
    qkv_mma<<<2048, 256, QKV_SMEM>>>(x);

    cudaFuncSetAttribute(attn_mma, cudaFuncAttributeMaxDynamicSharedMemorySize, ATTN_SMEM);
    dim3 agrid(2, BB);
    attn_mma<<<agrid, 256, ATTN_SMEM>>>(out);
}